// round 1
// baseline (speedup 1.0000x reference)
#include <cuda_runtime.h>
#include <cuda_bf16.h>
#include <cstdint>

// BatchRankingLoss: G=511 groups of d=256 decoys.
// loss = sum_{g,i,j} w_ij * max(0, 1 + y_ij*(o_i - o_j)) / (G*d*(d-1))
//   y_ij = -1 if (t_i - t_j) < 0 else +1
//   w_ij = |t_i - t_j| > 0.1
//
// Kernel 1: one CTA per group, 256 threads (thread = row i), writes group sum
//           to __device__ scratch.
// Kernel 2: single CTA reduces 511 group sums -> d_out[0] (deterministic,
//           no atomics, no init pass needed).

#define DECOYS 256
#define THRESH 0.1f

__device__ float g_group_sums[4096];  // scratch (>= G), static device mem (allowed)

__global__ __launch_bounds__(DECOYS) void group_pair_kernel(
    const float* __restrict__ o_in,   // [B,1] squeezed -> [B]
    const float* __restrict__ t_in)   // [B]
{
    __shared__ float2 ot[DECOYS];

    const int g    = blockIdx.x;
    const int i    = threadIdx.x;
    const int base = g * DECOYS;

    const float oi = o_in[base + i];
    const float ti = t_in[base + i];
    ot[i] = make_float2(oi, ti);
    __syncthreads();

    float acc = 0.0f;
#pragma unroll 8
    for (int j = 0; j < DECOYS; ++j) {
        const float2 v  = ot[j];           // broadcast LDS.64, conflict-free
        const float  dt = ti - v.y;        // t_i - t_j
        const float  dd = oi - v.x;        // o_i - o_j
        // y*do via sign-bit xor: y = -1 iff dt < 0. dt == -0.0 would mis-flip,
        // but |dt|==0 fails the weight gate so it never contributes.
        const uint32_t s_bits =
            __float_as_uint(dd) ^ (__float_as_uint(dt) & 0x80000000u);
        const float term = fmaxf(0.0f, 1.0f + __uint_as_float(s_bits));
        if (fabsf(dt) > THRESH) acc += term;   // predicated FADD
    }

    // warp reduce
#pragma unroll
    for (int off = 16; off > 0; off >>= 1)
        acc += __shfl_xor_sync(0xffffffffu, acc, off);

    __shared__ float wsum[DECOYS / 32];
    if ((i & 31) == 0) wsum[i >> 5] = acc;
    __syncthreads();

    if (i == 0) {
        float s = 0.0f;
#pragma unroll
        for (int w = 0; w < DECOYS / 32; ++w) s += wsum[w];
        g_group_sums[g] = s;
    }
}

__global__ __launch_bounds__(512) void reduce_kernel(float* __restrict__ out, int G)
{
    const int tid = threadIdx.x;
    float v = (tid < G) ? g_group_sums[tid] : 0.0f;

#pragma unroll
    for (int off = 16; off > 0; off >>= 1)
        v += __shfl_xor_sync(0xffffffffu, v, off);

    __shared__ float wsum[16];
    if ((tid & 31) == 0) wsum[tid >> 5] = v;
    __syncthreads();

    if (tid == 0) {
        float s = 0.0f;
#pragma unroll
        for (int w = 0; w < 16; ++w) s += wsum[w];
        const float inv_n =
            1.0f / ((float)G * (float)DECOYS * (float)(DECOYS - 1));
        out[0] = s * inv_n;
    }
}

extern "C" void kernel_launch(void* const* d_in, const int* in_sizes, int n_in,
                              void* d_out, int out_size)
{
    const float* o = (const float*)d_in[0];  // input  [B,1] f32
    const float* t = (const float*)d_in[1];  // gdt_ts [B]   f32
    float* out = (float*)d_out;

    const int B = in_sizes[1];       // gdt_ts element count = B
    const int K = B / DECOYS;        // 512
    const int G = K - 1;             // 511 (reference skips final group)

    group_pair_kernel<<<G, DECOYS>>>(o, t);
    reduce_kernel<<<1, 512>>>(out, G);
}